// round 1
// baseline (speedup 1.0000x reference)
#include <cuda_runtime.h>

#define N_NODES 100000
#define D 128
#define RNUM 3
#define KDIM (RNUM * D)   // 384

// ---------------- scratch (device globals; no allocation APIs allowed) --------
__device__ float g_agg[(size_t)N_NODES * KDIM];   // [N, 384] per-layer aggregation
__device__ float g_h1[(size_t)N_NODES * D];       // layer-1 output
__device__ float g_h2[(size_t)N_NODES * D];       // layer-2 output
__device__ float g_rdeg[RNUM * N_NODES];          // 1/max(deg,1) per relation
__device__ int   g_deg[RNUM * N_NODES];

// ---------------- degree pipeline -------------------------------------------
__global__ void zero_deg_kernel() {
    int i = blockIdx.x * blockDim.x + threadIdx.x;
    if (i < RNUM * N_NODES) g_deg[i] = 0;
}

__global__ void count_deg_kernel(const int* __restrict__ dst, int E) {
    int i = blockIdx.x * blockDim.x + threadIdx.x;
    if (i < RNUM * E) {
        int r = i / E;
        atomicAdd(&g_deg[r * N_NODES + dst[i]], 1);
    }
}

__global__ void make_rdeg_kernel() {
    int i = blockIdx.x * blockDim.x + threadIdx.x;
    if (i < RNUM * N_NODES) {
        int d = g_deg[i];
        g_rdeg[i] = 1.0f / (float)(d > 0 ? d : 1);
    }
}

// ---------------- per-layer kernels ------------------------------------------
__global__ void zero_agg_kernel() {
    int i = blockIdx.x * blockDim.x + threadIdx.x;
    if (i < N_NODES * KDIM / 4)
        ((float4*)g_agg)[i] = make_float4(0.f, 0.f, 0.f, 0.f);
}

// One warp per edge. Gathers a 128-float row of h (lane -> float4), scales by
// 1/deg(dst) of the relation, and RED-adds into agg[dst, r*128 : r*128+128].
__global__ void scatter_kernel(const float* __restrict__ xext, int in_sel,
                               const int* __restrict__ src,
                               const int* __restrict__ dst, int E) {
    const float* h = (in_sel == 0) ? xext : (in_sel == 1 ? g_h1 : g_h2);
    int gw   = (blockIdx.x * blockDim.x + threadIdx.x) >> 5;
    int lane = threadIdx.x & 31;
    if (gw >= RNUM * E) return;
    int r = gw / E;            // src/dst are [3, E] flat; gw indexes directly
    int s = __ldg(&src[gw]);
    int d = __ldg(&dst[gw]);
    float w = g_rdeg[r * N_NODES + d];

    float4 v = ((const float4*)(h + (size_t)s * D))[lane];
    float* o = g_agg + (size_t)d * KDIM + r * D + lane * 4;
    atomicAdd(o + 0, v.x * w);
    atomicAdd(o + 1, v.y * w);
    atomicAdd(o + 2, v.z * w);
    atomicAdd(o + 3, v.w * w);
}

// C[M,128] = relu( g_agg[M,384] @ W[384,128] + (b[0,:]+b[1,:]+b[2,:]) )
// Classic 128x128x8 SMEM-tiled SGEMM, 256 threads, 8x8 microtile.
__global__ __launch_bounds__(256)
void gemm_bias_relu_kernel(const float* __restrict__ W,   // [384,128] (W_l flat)
                           const float* __restrict__ b,   // [3,128]
                           float* __restrict__ outext, int out_sel, int M) {
    __shared__ float As[8][128];   // [k][m] (transposed on store)
    __shared__ float Bs[8][128];   // [k][n]

    float* C = (out_sel == 3) ? outext : (out_sel == 1 ? g_h1 : g_h2);
    const float* A = g_agg;

    int tid      = threadIdx.x;
    int blockRow = blockIdx.x * 128;

    // A-tile load mapping: 128 rows x 8 k -> 256 threads x float4 along k
    int arow = tid >> 1;
    int acol = (tid & 1) * 4;
    // B-tile load mapping: 8 k-rows x 128 cols -> 256 threads x float4 along n
    int brow = tid >> 5;
    int bcol = (tid & 31) * 4;

    int tx = tid & 15;   // 16 col-groups of 8
    int ty = tid >> 4;   // 16 row-groups of 8

    int  gm     = blockRow + arow;
    bool avalid = gm < M;
    const float4* Arow4 = (const float4*)(A + (size_t)gm * KDIM);

    float acc[8][8];
#pragma unroll
    for (int i = 0; i < 8; i++)
#pragma unroll
        for (int j = 0; j < 8; j++) acc[i][j] = 0.f;

    for (int k0 = 0; k0 < KDIM; k0 += 8) {
        float4 av = avalid ? Arow4[(k0 + acol) >> 2] : make_float4(0.f, 0.f, 0.f, 0.f);
        float4 bv = *(const float4*)(W + (size_t)(k0 + brow) * 128 + bcol);

        __syncthreads();   // protect previous iteration's reads
        As[acol + 0][arow] = av.x;
        As[acol + 1][arow] = av.y;
        As[acol + 2][arow] = av.z;
        As[acol + 3][arow] = av.w;
        *(float4*)&Bs[brow][bcol] = bv;
        __syncthreads();

#pragma unroll
        for (int k = 0; k < 8; k++) {
            float ra[8], rb[8];
#pragma unroll
            for (int i = 0; i < 8; i++) ra[i] = As[k][ty * 8 + i];
#pragma unroll
            for (int j = 0; j < 8; j++) rb[j] = Bs[k][tx * 8 + j];
#pragma unroll
            for (int i = 0; i < 8; i++)
#pragma unroll
                for (int j = 0; j < 8; j++) acc[i][j] += ra[i] * rb[j];
        }
    }

    // bias (summed across the 3 relations) + relu + store
    float bias[8];
#pragma unroll
    for (int j = 0; j < 8; j++) {
        int col = tx * 8 + j;
        bias[j] = b[col] + b[128 + col] + b[256 + col];
    }
#pragma unroll
    for (int i = 0; i < 8; i++) {
        int row = blockRow + ty * 8 + i;
        if (row < M) {
            float4 v0, v1;
            float t;
            t = acc[i][0] + bias[0]; v0.x = t > 0.f ? t : 0.f;
            t = acc[i][1] + bias[1]; v0.y = t > 0.f ? t : 0.f;
            t = acc[i][2] + bias[2]; v0.z = t > 0.f ? t : 0.f;
            t = acc[i][3] + bias[3]; v0.w = t > 0.f ? t : 0.f;
            t = acc[i][4] + bias[4]; v1.x = t > 0.f ? t : 0.f;
            t = acc[i][5] + bias[5]; v1.y = t > 0.f ? t : 0.f;
            t = acc[i][6] + bias[6]; v1.z = t > 0.f ? t : 0.f;
            t = acc[i][7] + bias[7]; v1.w = t > 0.f ? t : 0.f;
            float4* crow = (float4*)(C + (size_t)row * 128 + tx * 8);
            crow[0] = v0;
            crow[1] = v1;
        }
    }
}

// ---------------- launch ------------------------------------------------------
extern "C" void kernel_launch(void* const* d_in, const int* in_sizes, int n_in,
                              void* d_out, int out_size) {
    const float* x   = (const float*)d_in[0];
    const int*   src = (const int*)d_in[1];
    const int*   dst = (const int*)d_in[2];
    const float* W1  = (const float*)d_in[3];
    const float* b1  = (const float*)d_in[4];
    const float* W2  = (const float*)d_in[5];
    const float* b2  = (const float*)d_in[6];
    const float* W3  = (const float*)d_in[7];
    const float* b3  = (const float*)d_in[8];
    float* out = (float*)d_out;

    int E = in_sizes[1] / RNUM;

    int degN        = RNUM * N_NODES;
    int deg_blocks  = (degN + 255) / 256;
    int cnt_blocks  = (RNUM * E + 255) / 256;
    int aggQuads    = N_NODES * KDIM / 4;
    int zer_blocks  = (aggQuads + 255) / 256;
    int scat_blocks = (RNUM * E * 32 + 255) / 256;
    int gemm_blocks = (N_NODES + 127) / 128;

    // degrees (graph identical across all 3 layers)
    zero_deg_kernel<<<deg_blocks, 256>>>();
    count_deg_kernel<<<cnt_blocks, 256>>>(dst, E);
    make_rdeg_kernel<<<deg_blocks, 256>>>();

    // layer 1: x -> g_h1
    zero_agg_kernel<<<zer_blocks, 256>>>();
    scatter_kernel<<<scat_blocks, 256>>>(x, 0, src, dst, E);
    gemm_bias_relu_kernel<<<gemm_blocks, 256>>>(W1, b1, out, 1, N_NODES);

    // layer 2: g_h1 -> g_h2
    zero_agg_kernel<<<zer_blocks, 256>>>();
    scatter_kernel<<<scat_blocks, 256>>>(x, 1, src, dst, E);
    gemm_bias_relu_kernel<<<gemm_blocks, 256>>>(W2, b2, out, 2, N_NODES);

    // layer 3: g_h2 -> d_out
    zero_agg_kernel<<<zer_blocks, 256>>>();
    scatter_kernel<<<scat_blocks, 256>>>(x, 2, src, dst, E);
    gemm_bias_relu_kernel<<<gemm_blocks, 256>>>(W3, b3, out, 3, N_NODES);
}

// round 2
// speedup vs baseline: 1.3870x; 1.3870x over previous
#include <cuda_runtime.h>

#define N_NODES 100000
#define D 128
#define RNUM 3
#define KDIM (RNUM * D)            // 384
#define E_MAX 200000
#define NTOT (RNUM * N_NODES)      // 300000
#define SCAN_GRAIN 1024
#define SCAN_NBLK ((NTOT + SCAN_GRAIN - 1) / SCAN_GRAIN)   // 293

// ---------------- scratch (device globals; no allocation APIs allowed) --------
__device__ float g_agg[(size_t)N_NODES * KDIM];   // [N, 384] per-layer aggregation
__device__ float g_h1[(size_t)N_NODES * D];       // layer-1 output
__device__ float g_h2[(size_t)N_NODES * D];       // layer-2 output
__device__ float g_rdeg[NTOT];                    // 1/max(deg,1) per (rel, node)
__device__ int   g_deg[NTOT];                     // in-degree per (rel, node)
__device__ int   g_off[NTOT];                     // CSR row offsets (exclusive scan of deg)
__device__ int   g_blocksum[SCAN_NBLK];
__device__ int   g_cursor[NTOT];                  // fill cursors
__device__ int   g_esrc[RNUM * E_MAX];            // CSR: src ids grouped by (rel, dst)

// ---------------- degree pipeline -------------------------------------------
__global__ void zero_deg_kernel() {
    int i = blockIdx.x * blockDim.x + threadIdx.x;
    if (i < NTOT) g_deg[i] = 0;
}

__global__ void count_deg_kernel(const int* __restrict__ dst, int E) {
    int i = blockIdx.x * blockDim.x + threadIdx.x;
    if (i < RNUM * E) {
        int r = i / E;
        atomicAdd(&g_deg[r * N_NODES + dst[i]], 1);
    }
}

__global__ void make_rdeg_kernel() {
    int i = blockIdx.x * blockDim.x + threadIdx.x;
    if (i < NTOT) {
        int d = g_deg[i];
        g_rdeg[i] = 1.0f / (float)(d > 0 ? d : 1);
    }
}

// ---------------- exclusive scan of g_deg -> g_off ---------------------------
// Pass 1: per-block (1024-element grain, 256 threads x 4 elems) local exclusive
// scan; block total into g_blocksum.
__global__ void scan_local_kernel() {
    __shared__ int sh[256];
    int t = threadIdx.x;
    int base = blockIdx.x * SCAN_GRAIN + t * 4;
    int v[4];
#pragma unroll
    for (int i = 0; i < 4; i++) {
        int idx = base + i;
        v[i] = (idx < NTOT) ? g_deg[idx] : 0;
    }
    int s = v[0] + v[1] + v[2] + v[3];
    sh[t] = s;
    __syncthreads();
    for (int off = 1; off < 256; off <<= 1) {
        int x = sh[t];
        int y = (t >= off) ? sh[t - off] : 0;
        __syncthreads();
        sh[t] = x + y;
        __syncthreads();
    }
    int excl = (t > 0) ? sh[t - 1] : 0;
    if (t == 255) g_blocksum[blockIdx.x] = sh[255];
    int run = excl;
#pragma unroll
    for (int i = 0; i < 4; i++) {
        int idx = base + i;
        if (idx < NTOT) g_off[idx] = run;
        run += v[i];
    }
}

// Pass 2: single block scans the 293 block sums (exclusive).
__global__ void scan_blocksums_kernel() {
    __shared__ int sh[512];
    int t = threadIdx.x;
    int v = (t < SCAN_NBLK) ? g_blocksum[t] : 0;
    sh[t] = v;
    __syncthreads();
    for (int off = 1; off < 512; off <<= 1) {
        int x = sh[t];
        int y = (t >= off) ? sh[t - off] : 0;
        __syncthreads();
        sh[t] = x + y;
        __syncthreads();
    }
    if (t < SCAN_NBLK) g_blocksum[t] = (t > 0) ? sh[t - 1] : 0;
}

// Pass 3: add block offsets; also zero the fill cursors.
__global__ void scan_add_kernel() {
    int i = blockIdx.x * blockDim.x + threadIdx.x;
    if (i < NTOT) {
        g_off[i] += g_blocksum[i >> 10];
        g_cursor[i] = 0;
    }
}

// Bin edges into CSR slots (atomics only on 300k int cursors).
__global__ void fill_csr_kernel(const int* __restrict__ src,
                                const int* __restrict__ dst, int E) {
    int i = blockIdx.x * blockDim.x + threadIdx.x;
    if (i < RNUM * E) {
        int r = i / E;
        int slot = r * N_NODES + dst[i];
        int pos = atomicAdd(&g_cursor[slot], 1);
        g_esrc[g_off[slot] + pos] = src[i];
    }
}

// ---------------- gather (pull) aggregation -----------------------------------
// One warp per node: accumulate the degree-normalized mean of incoming h[src]
// rows for each of the 3 relations (12 floats/lane in registers), then write
// the full agg[node, 0:384] row once, coalesced. No feature atomics.
__global__ void gather_kernel(const float* __restrict__ xext, int in_sel) {
    const float* h = (in_sel == 0) ? xext : (in_sel == 1 ? g_h1 : g_h2);
    int node = (blockIdx.x * blockDim.x + threadIdx.x) >> 5;
    int lane = threadIdx.x & 31;
    if (node >= N_NODES) return;

#pragma unroll
    for (int r = 0; r < RNUM; r++) {
        int slot = r * N_NODES + node;
        int beg = g_off[slot];
        int end = beg + g_deg[slot];
        float4 acc = make_float4(0.f, 0.f, 0.f, 0.f);
        for (int e = beg; e < end; e++) {
            int s = __ldg(&g_esrc[e]);
            float4 v = __ldg(&((const float4*)(h + (size_t)s * D))[lane]);
            acc.x += v.x; acc.y += v.y; acc.z += v.z; acc.w += v.w;
        }
        float w = g_rdeg[slot];
        acc.x *= w; acc.y *= w; acc.z *= w; acc.w *= w;
        ((float4*)(g_agg + (size_t)node * KDIM + r * D))[lane] = acc;
    }
}

// ---------------- GEMM + bias + relu -----------------------------------------
// C[M,128] = relu( g_agg[M,384] @ W[384,128] + (b[0,:]+b[1,:]+b[2,:]) )
__global__ __launch_bounds__(256)
void gemm_bias_relu_kernel(const float* __restrict__ W,   // [384,128]
                           const float* __restrict__ b,   // [3,128]
                           float* __restrict__ outext, int out_sel, int M) {
    __shared__ float As[8][128];   // [k][m]
    __shared__ float Bs[8][128];   // [k][n]

    float* C = (out_sel == 3) ? outext : (out_sel == 1 ? g_h1 : g_h2);
    const float* A = g_agg;

    int tid      = threadIdx.x;
    int blockRow = blockIdx.x * 128;

    int arow = tid >> 1;
    int acol = (tid & 1) * 4;
    int brow = tid >> 5;
    int bcol = (tid & 31) * 4;

    int tx = tid & 15;
    int ty = tid >> 4;

    int  gm     = blockRow + arow;
    bool avalid = gm < M;
    const float4* Arow4 = (const float4*)(A + (size_t)gm * KDIM);

    float acc[8][8];
#pragma unroll
    for (int i = 0; i < 8; i++)
#pragma unroll
        for (int j = 0; j < 8; j++) acc[i][j] = 0.f;

    for (int k0 = 0; k0 < KDIM; k0 += 8) {
        float4 av = avalid ? Arow4[(k0 + acol) >> 2] : make_float4(0.f, 0.f, 0.f, 0.f);
        float4 bv = *(const float4*)(W + (size_t)(k0 + brow) * 128 + bcol);

        __syncthreads();
        As[acol + 0][arow] = av.x;
        As[acol + 1][arow] = av.y;
        As[acol + 2][arow] = av.z;
        As[acol + 3][arow] = av.w;
        *(float4*)&Bs[brow][bcol] = bv;
        __syncthreads();

#pragma unroll
        for (int k = 0; k < 8; k++) {
            float ra[8], rb[8];
#pragma unroll
            for (int i = 0; i < 8; i++) ra[i] = As[k][ty * 8 + i];
#pragma unroll
            for (int j = 0; j < 8; j++) rb[j] = Bs[k][tx * 8 + j];
#pragma unroll
            for (int i = 0; i < 8; i++)
#pragma unroll
                for (int j = 0; j < 8; j++) acc[i][j] += ra[i] * rb[j];
        }
    }

    float bias[8];
#pragma unroll
    for (int j = 0; j < 8; j++) {
        int col = tx * 8 + j;
        bias[j] = b[col] + b[128 + col] + b[256 + col];
    }
#pragma unroll
    for (int i = 0; i < 8; i++) {
        int row = blockRow + ty * 8 + i;
        if (row < M) {
            float4 v0, v1;
            float t;
            t = acc[i][0] + bias[0]; v0.x = t > 0.f ? t : 0.f;
            t = acc[i][1] + bias[1]; v0.y = t > 0.f ? t : 0.f;
            t = acc[i][2] + bias[2]; v0.z = t > 0.f ? t : 0.f;
            t = acc[i][3] + bias[3]; v0.w = t > 0.f ? t : 0.f;
            t = acc[i][4] + bias[4]; v1.x = t > 0.f ? t : 0.f;
            t = acc[i][5] + bias[5]; v1.y = t > 0.f ? t : 0.f;
            t = acc[i][6] + bias[6]; v1.z = t > 0.f ? t : 0.f;
            t = acc[i][7] + bias[7]; v1.w = t > 0.f ? t : 0.f;
            float4* crow = (float4*)(C + (size_t)row * 128 + tx * 8);
            crow[0] = v0;
            crow[1] = v1;
        }
    }
}

// ---------------- launch ------------------------------------------------------
extern "C" void kernel_launch(void* const* d_in, const int* in_sizes, int n_in,
                              void* d_out, int out_size) {
    const float* x   = (const float*)d_in[0];
    const int*   src = (const int*)d_in[1];
    const int*   dst = (const int*)d_in[2];
    const float* W1  = (const float*)d_in[3];
    const float* b1  = (const float*)d_in[4];
    const float* W2  = (const float*)d_in[5];
    const float* b2  = (const float*)d_in[6];
    const float* W3  = (const float*)d_in[7];
    const float* b3  = (const float*)d_in[8];
    float* out = (float*)d_out;

    int E = in_sizes[1] / RNUM;

    int deg_blocks  = (NTOT + 255) / 256;
    int cnt_blocks  = (RNUM * E + 255) / 256;
    int gat_blocks  = (N_NODES * 32 + 255) / 256;
    int gemm_blocks = (N_NODES + 127) / 128;

    // ---- CSR build (graph identical across all 3 layers) ----
    zero_deg_kernel<<<deg_blocks, 256>>>();
    count_deg_kernel<<<cnt_blocks, 256>>>(dst, E);
    make_rdeg_kernel<<<deg_blocks, 256>>>();
    scan_local_kernel<<<SCAN_NBLK, 256>>>();
    scan_blocksums_kernel<<<1, 512>>>();
    scan_add_kernel<<<deg_blocks, 256>>>();
    fill_csr_kernel<<<cnt_blocks, 256>>>(src, dst, E);

    // ---- layer 1: x -> g_h1 ----
    gather_kernel<<<gat_blocks, 256>>>(x, 0);
    gemm_bias_relu_kernel<<<gemm_blocks, 256>>>(W1, b1, out, 1, N_NODES);

    // ---- layer 2: g_h1 -> g_h2 ----
    gather_kernel<<<gat_blocks, 256>>>(x, 1);
    gemm_bias_relu_kernel<<<gemm_blocks, 256>>>(W2, b2, out, 2, N_NODES);

    // ---- layer 3: g_h2 -> d_out ----
    gather_kernel<<<gat_blocks, 256>>>(x, 2);
    gemm_bias_relu_kernel<<<gemm_blocks, 256>>>(W3, b3, out, 3, N_NODES);
}